// round 3
// baseline (speedup 1.0000x reference)
#include <cuda_runtime.h>
#include <math.h>

#define NB 8
#define NC 64
#define NS 256
#define NM 32
#define HW (NS*NS)

// ---------------- static device scratch (no allocation) ----------------
__device__ float g_basis[NS*64];        // fwd DFT: [t][2k]=cos(2pi kt/N), [2k+1]=-sin
__device__ float g_ibasis[NS*64];       // inv DFT: [t][2k]=a_k cos, [2k+1]=-a_k sin (k=0 imag->0)
__device__ float g_whT[2][NM*NC*NC];    // [re/im][k][i][o]
__device__ float g_wwT[2][NM*NC*NC];
__device__ float g_Xh[(size_t)NB*NC*64*NS];   // [b][i][ko][w]  (ko: even=re, odd=im)
__device__ float g_Xw[(size_t)NB*NC*64*NS];   // [b][i][ko][h]
__device__ float g_Oh[(size_t)NB*NC*64*NS];   // [b][o][ko][w]
__device__ float g_Ow[(size_t)NB*NC*64*NS];   // [b][o][ko][h]
__device__ float g_f [(size_t)NB*NC*HW];      // spectral conv result [b][c][h][w]

// ---------------- init: basis tables + weight transposes ----------------
__global__ void initK(const float* __restrict__ whr, const float* __restrict__ whi,
                      const float* __restrict__ wwr, const float* __restrict__ wwi) {
    int idx = blockIdx.x * 256 + threadIdx.x;       // grid covers 131072
    if (idx < NS*64) {
        int t = idx >> 6, ko = idx & 63, k = ko >> 1;
        float s, c;
        sincospif((float)((k * t) & 255) / 128.0f, &s, &c);   // 2*pi*k*t/256
        g_basis[idx] = (ko & 1) ? -s : c;
        float a = (k == 0) ? (1.0f/NS) : (2.0f/NS);
        g_ibasis[idx] = (ko & 1) ? ((k == 0) ? 0.0f : -a*s) : a*c;
    }
    if (idx < NM*NC*NC) {
        int k = idx >> 12, r = idx & 4095, i = r >> 6, o = r & 63;
        int src = (i*NC + o)*NM + k;
        g_whT[0][idx] = whr[src];  g_whT[1][idx] = whi[src];
        g_wwT[0][idx] = wwr[src];  g_wwT[1][idx] = wwi[src];
    }
}

// ---------------- forward DFT over H: Xh[b,i,ko,w] = sum_h basis[ko,h]*x[b,i,h,w] ----------------
__global__ void fdftH(const float* __restrict__ x) {
    __shared__ float sA[64][65];   // [h][ko]
    __shared__ float sB[64][65];   // [h][w]
    int slab = blockIdx.x;                 // b*64 + i
    int w0 = blockIdx.y * 64;
    const float* xp = x + (size_t)slab * HW;
    int tx = threadIdx.x & 15, ty = threadIdx.x >> 4;
    float acc[4][4] = {};
    for (int hc = 0; hc < NS; hc += 64) {
        for (int idx = threadIdx.x; idx < 4096; idx += 256) {
            int r = idx >> 6, c = idx & 63;
            sA[r][c] = g_basis[(hc + r)*64 + c];
            sB[r][c] = xp[(size_t)(hc + r)*NS + w0 + c];
        }
        __syncthreads();
        #pragma unroll 8
        for (int h = 0; h < 64; h++) {
            float a[4], bv[4];
            #pragma unroll
            for (int j = 0; j < 4; j++) a[j]  = sA[h][ty*4 + j];
            #pragma unroll
            for (int d = 0; d < 4; d++) bv[d] = sB[h][tx*4 + d];
            #pragma unroll
            for (int j = 0; j < 4; j++)
                #pragma unroll
                for (int d = 0; d < 4; d++)
                    acc[j][d] = fmaf(a[j], bv[d], acc[j][d]);
        }
        __syncthreads();
    }
    float* dst = g_Xh + (size_t)slab * 64 * NS;
    #pragma unroll
    for (int j = 0; j < 4; j++)
        #pragma unroll
        for (int d = 0; d < 4; d++)
            dst[(ty*4 + j)*NS + w0 + tx*4 + d] = acc[j][d];
}

// ---------------- forward DFT over W: Xw[b,i,ko,h] = sum_w basis[ko,w]*x[b,i,h,w] ----------------
__global__ void fdftW(const float* __restrict__ x) {
    __shared__ float sA[64][65];   // [w][ko]
    __shared__ float sB[64][65];   // [w][h]
    int slab = blockIdx.x;
    int h0 = blockIdx.y * 64;
    const float* xp = x + (size_t)slab * HW;
    int tx = threadIdx.x & 15, ty = threadIdx.x >> 4;
    float acc[4][4] = {};
    for (int wc = 0; wc < NS; wc += 64) {
        for (int idx = threadIdx.x; idx < 4096; idx += 256) {
            int r = idx >> 6, c = idx & 63;          // r = h-offset, c = w-offset
            sA[r][c] = g_basis[(wc + r)*64 + c];
            sB[c][r] = xp[(size_t)(h0 + r)*NS + wc + c];   // transpose into [w][h]
        }
        __syncthreads();
        #pragma unroll 8
        for (int w = 0; w < 64; w++) {
            float a[4], bv[4];
            #pragma unroll
            for (int j = 0; j < 4; j++) a[j]  = sA[w][ty*4 + j];
            #pragma unroll
            for (int d = 0; d < 4; d++) bv[d] = sB[w][tx*4 + d];
            #pragma unroll
            for (int j = 0; j < 4; j++)
                #pragma unroll
                for (int d = 0; d < 4; d++)
                    acc[j][d] = fmaf(a[j], bv[d], acc[j][d]);
        }
        __syncthreads();
    }
    float* dst = g_Xw + (size_t)slab * 64 * NS;
    #pragma unroll
    for (int j = 0; j < 4; j++)
        #pragma unroll
        for (int d = 0; d < 4; d++)
            dst[(ty*4 + j)*NS + h0 + tx*4 + d] = acc[j][d];
}

// ---------------- per-mode complex channel mix: O[o,col] = sum_i W[i,o]*X[i,col] ----------------
__global__ void mixK(int br) {
    __shared__ float sWr[32][65], sWi[32][65], sXr[32][65], sXi[32][65];
    const float* Xin = br ? g_Xw : g_Xh;
    const float* Wr  = br ? g_wwT[0] : g_whT[0];
    const float* Wi  = br ? g_wwT[1] : g_whT[1];
    float* Out       = br ? g_Ow : g_Oh;
    int b = blockIdx.x >> 5, k = blockIdx.x & 31;
    int c0 = blockIdx.y * 64;
    int tx = threadIdx.x & 15, ty = threadIdx.x >> 4;
    float accr[4][4] = {}, acci[4][4] = {};
    for (int ic = 0; ic < 64; ic += 32) {
        for (int idx = threadIdx.x; idx < 2048; idx += 256) {
            int i = idx >> 6, c = idx & 63;
            sWr[i][c] = Wr[(k*64 + ic + i)*64 + c];
            sWi[i][c] = Wi[(k*64 + ic + i)*64 + c];
            const float* xb = Xin + ((size_t)(b*64 + ic + i)*64 + 2*k)*NS + c0;
            sXr[i][c] = xb[c];
            sXi[i][c] = xb[NS + c];
        }
        __syncthreads();
        #pragma unroll 4
        for (int i = 0; i < 32; i++) {
            float ar[4], ai[4], br_[4], bi[4];
            #pragma unroll
            for (int j = 0; j < 4; j++) { ar[j] = sWr[i][ty*4+j]; ai[j] = sWi[i][ty*4+j]; }
            #pragma unroll
            for (int d = 0; d < 4; d++) { br_[d] = sXr[i][tx*4+d]; bi[d] = sXi[i][tx*4+d]; }
            #pragma unroll
            for (int j = 0; j < 4; j++)
                #pragma unroll
                for (int d = 0; d < 4; d++) {
                    accr[j][d] = fmaf(ar[j], br_[d], accr[j][d]);
                    accr[j][d] = fmaf(-ai[j], bi[d], accr[j][d]);
                    acci[j][d] = fmaf(ar[j], bi[d], acci[j][d]);
                    acci[j][d] = fmaf(ai[j], br_[d], acci[j][d]);
                }
        }
        __syncthreads();
    }
    #pragma unroll
    for (int j = 0; j < 4; j++)
        #pragma unroll
        for (int d = 0; d < 4; d++) {
            float* ob = Out + ((size_t)(b*64 + ty*4 + j)*64 + 2*k)*NS + c0 + tx*4 + d;
            ob[0]  = accr[j][d];
            ob[NS] = acci[j][d];
        }
}

// ---------------- inverse DFT over H: f[h,w] = sum_ko ibasis[h,ko]*Oh[ko,w] ----------------
__global__ void invH() {
    __shared__ float sA[64][65];   // [ko][h]
    __shared__ float sB[64][65];   // [ko][w]
    int slab = blockIdx.x;
    int h0 = (blockIdx.y >> 2) * 64, w0 = (blockIdx.y & 3) * 64;
    int tx = threadIdx.x & 15, ty = threadIdx.x >> 4;
    const float* O = g_Oh + (size_t)slab * 64 * NS;
    for (int idx = threadIdx.x; idx < 4096; idx += 256) {
        int r = idx >> 6, c = idx & 63;
        sA[c][r] = g_ibasis[(h0 + r)*64 + c];
        sB[r][c] = O[r*NS + w0 + c];
    }
    __syncthreads();
    float acc[4][4] = {};
    #pragma unroll 8
    for (int ko = 0; ko < 64; ko++) {
        float a[4], bv[4];
        #pragma unroll
        for (int j = 0; j < 4; j++) a[j]  = sA[ko][ty*4 + j];
        #pragma unroll
        for (int d = 0; d < 4; d++) bv[d] = sB[ko][tx*4 + d];
        #pragma unroll
        for (int j = 0; j < 4; j++)
            #pragma unroll
            for (int d = 0; d < 4; d++)
                acc[j][d] = fmaf(a[j], bv[d], acc[j][d]);
    }
    float* fp = g_f + (size_t)slab * HW;
    #pragma unroll
    for (int j = 0; j < 4; j++)
        #pragma unroll
        for (int d = 0; d < 4; d++)
            fp[(size_t)(h0 + ty*4 + j)*NS + w0 + tx*4 + d] = acc[j][d];
}

// ---------------- inverse DFT over W: f[h,w] += sum_ko Ow[ko,h]*ibasis[w,ko] ----------------
__global__ void invW() {
    __shared__ float sA[64][65];   // [ko][h]
    __shared__ float sB[64][65];   // [ko][w]
    int slab = blockIdx.x;
    int h0 = (blockIdx.y >> 2) * 64, w0 = (blockIdx.y & 3) * 64;
    int tx = threadIdx.x & 15, ty = threadIdx.x >> 4;
    const float* O = g_Ow + (size_t)slab * 64 * NS;
    for (int idx = threadIdx.x; idx < 4096; idx += 256) {
        int r = idx >> 6, c = idx & 63;
        sA[r][c] = O[r*NS + h0 + c];                 // [ko][h] direct
        sB[c][r] = g_ibasis[(w0 + r)*64 + c];        // [ko][w] via transpose
    }
    __syncthreads();
    float acc[4][4] = {};
    #pragma unroll 8
    for (int ko = 0; ko < 64; ko++) {
        float a[4], bv[4];
        #pragma unroll
        for (int j = 0; j < 4; j++) a[j]  = sA[ko][ty*4 + j];
        #pragma unroll
        for (int d = 0; d < 4; d++) bv[d] = sB[ko][tx*4 + d];
        #pragma unroll
        for (int j = 0; j < 4; j++)
            #pragma unroll
            for (int d = 0; d < 4; d++)
                acc[j][d] = fmaf(a[j], bv[d], acc[j][d]);
    }
    float* fp = g_f + (size_t)slab * HW;
    #pragma unroll
    for (int j = 0; j < 4; j++)
        #pragma unroll
        for (int d = 0; d < 4; d++)
            fp[(size_t)(h0 + ty*4 + j)*NS + w0 + tx*4 + d] += acc[j][d];
}

// ---------------- fused FFN: fc1 + relu + LN + fc2 + residual ----------------
__global__ void ffnK(const float* __restrict__ x,
                     const float* __restrict__ w1, const float* __restrict__ b1,
                     const float* __restrict__ lng, const float* __restrict__ lnb,
                     const float* __restrict__ w2, const float* __restrict__ b2,
                     float* __restrict__ out) {
    __shared__ float sF[64*64];     // [c][px]
    __shared__ float sT[64*128];    // [px][j], later reused (padded) for t2 [o][px]
    int b = blockIdx.x >> 10;
    int p0 = (blockIdx.x & 1023) * 64;
    int tid = threadIdx.x;

    for (int idx = tid; idx < 4096; idx += 256) {
        int c = idx >> 6, px = idx & 63;
        sF[c*64 + px] = g_f[((size_t)(b*64 + c) << 16) + p0 + px];
    }
    __syncthreads();

    // stage 1: t1 = relu(f @ w1 + b1)
    {
        int tx = tid & 31, ty = tid >> 5;       // tx -> 4 outputs, ty -> 8 pixels
        float acc[8][4] = {};
        for (int c = 0; c < 64; c++) {
            float wv[4];
            #pragma unroll
            for (int j = 0; j < 4; j++) wv[j] = w1[c*128 + tx*4 + j];
            #pragma unroll
            for (int p = 0; p < 8; p++) {
                float fv = sF[c*64 + ty*8 + p];
                #pragma unroll
                for (int j = 0; j < 4; j++) acc[p][j] = fmaf(fv, wv[j], acc[p][j]);
            }
        }
        #pragma unroll
        for (int p = 0; p < 8; p++)
            #pragma unroll
            for (int j = 0; j < 4; j++) {
                float v = acc[p][j] + b1[tx*4 + j];
                sT[(ty*8 + p)*128 + tx*4 + j] = fmaxf(v, 0.0f);
            }
    }
    __syncthreads();

    // LayerNorm over 128 features, one warp -> 8 pixels
    {
        int wid = tid >> 5, lane = tid & 31;
        for (int p8 = 0; p8 < 8; p8++) {
            int px = wid*8 + p8;
            float v[4], s1 = 0.f, s2 = 0.f;
            #pragma unroll
            for (int j = 0; j < 4; j++) {
                v[j] = sT[px*128 + lane*4 + j];
                s1 += v[j]; s2 += v[j]*v[j];
            }
            #pragma unroll
            for (int o = 16; o > 0; o >>= 1) {
                s1 += __shfl_xor_sync(0xFFFFFFFFu, s1, o);
                s2 += __shfl_xor_sync(0xFFFFFFFFu, s2, o);
            }
            float mu  = s1 * (1.0f/128.0f);
            float var = s2 * (1.0f/128.0f) - mu*mu;
            float inv = rsqrtf(var + 1e-5f);
            #pragma unroll
            for (int j = 0; j < 4; j++)
                sT[px*128 + lane*4 + j] =
                    (v[j] - mu) * inv * lng[lane*4 + j] + lnb[lane*4 + j];
        }
    }
    __syncthreads();

    // stage 2: t2 = t1n @ w2
    float acc2[4][4] = {};
    {
        int tx = tid & 15, ty = tid >> 4;       // tx -> 4 outs, ty -> 4 pixels
        for (int kk = 0; kk < 128; kk++) {
            float wv[4];
            #pragma unroll
            for (int j = 0; j < 4; j++) wv[j] = w2[kk*64 + tx*4 + j];
            #pragma unroll
            for (int d = 0; d < 4; d++) {
                float t = sT[(ty*4 + d)*128 + kk];
                #pragma unroll
                for (int j = 0; j < 4; j++) acc2[d][j] = fmaf(t, wv[j], acc2[d][j]);
            }
        }
    }
    __syncthreads();
    // stash t2 into sT as padded [o][px] for coalesced writeout
    {
        int tx = tid & 15, ty = tid >> 4;
        #pragma unroll
        for (int d = 0; d < 4; d++)
            #pragma unroll
            for (int j = 0; j < 4; j++)
                sT[(tx*4 + j)*65 + ty*4 + d] = acc2[d][j];
    }
    __syncthreads();
    for (int idx = tid; idx < 4096; idx += 256) {
        int o = idx >> 6, px = idx & 63;
        size_t gg = ((size_t)(b*64 + o) << 16) + p0 + px;
        out[gg] = sT[o*65 + px] + b2[o] + x[gg];
    }
}

// ---------------- launch ----------------
extern "C" void kernel_launch(void* const* d_in, const int* in_sizes, int n_in,
                              void* d_out, int out_size) {
    const float* x    = (const float*)d_in[0];
    const float* whr  = (const float*)d_in[1];
    const float* whi  = (const float*)d_in[2];
    const float* wwr  = (const float*)d_in[3];
    const float* wwi  = (const float*)d_in[4];
    const float* fc1w = (const float*)d_in[5];
    const float* fc1b = (const float*)d_in[6];
    const float* lng  = (const float*)d_in[7];
    const float* lnb  = (const float*)d_in[8];
    const float* fc2w = (const float*)d_in[9];
    const float* fc2b = (const float*)d_in[10];
    float* out = (float*)d_out;

    initK<<<512, 256>>>(whr, whi, wwr, wwi);
    fdftH<<<dim3(512, 4), 256>>>(x);
    fdftW<<<dim3(512, 4), 256>>>(x);
    mixK<<<dim3(256, 4), 256>>>(0);
    mixK<<<dim3(256, 4), 256>>>(1);
    invH<<<dim3(512, 16), 256>>>();
    invW<<<dim3(512, 16), 256>>>();
    ffnK<<<8192, 256>>>(x, fc1w, fc1b, lng, lnb, fc2w, fc2b, out);
}

// round 4
// speedup vs baseline: 1.0583x; 1.0583x over previous
#include <cuda_runtime.h>
#include <math.h>

#define NB 8
#define NC 64
#define NS 256
#define NM 32
#define HW (NS*NS)

typedef unsigned long long u64;
__device__ __forceinline__ u64 pk2(float lo, float hi) {
    u64 r; asm("mov.b64 %0,{%1,%2};" : "=l"(r) : "f"(lo), "f"(hi)); return r;
}
__device__ __forceinline__ void fma2(u64 &d, u64 a, u64 b) {
    asm("fma.rn.f32x2 %0,%1,%2,%0;" : "+l"(d) : "l"(a), "l"(b));
}
__device__ __forceinline__ void up2(u64 v, float &lo, float &hi) {
    asm("mov.b64 {%0,%1},%2;" : "=f"(lo), "=f"(hi) : "l"(v));
}

// ---------------- static device scratch (no allocation) ----------------
__device__ float g_basis[NS*64];       // fwd DFT [t][ko]: even=cos, odd=-sin
__device__ float g_ibasisT[64*NS];     // inv DFT transposed [ko][t] (irfft weights folded)
__device__ float g_whT[2][NM*NC*NC];   // [re/im][k][i][o]
__device__ float g_wwT[2][NM*NC*NC];
__device__ float g_Xh[(size_t)NB*NC*64*NS];   // [b][i][ko][w]
__device__ float g_Xw[(size_t)NB*NC*64*NS];   // [b][i][ko][h]
__device__ float g_Oh[(size_t)NB*NC*64*NS];   // [b][o][ko][w]
__device__ float g_Ow[(size_t)NB*NC*64*NS];   // [b][o][ko][h]
__device__ float g_f [(size_t)NB*NC*HW];      // spectral conv result

// ---------------- init ----------------
__global__ void initK(const float* __restrict__ whr, const float* __restrict__ whi,
                      const float* __restrict__ wwr, const float* __restrict__ wwi) {
    int idx = blockIdx.x * 256 + threadIdx.x;   // grid covers 131072
    if (idx < NS*64) {
        int t = idx >> 6, ko = idx & 63, k = ko >> 1;
        float s, c;
        sincospif((float)((k * t) & 255) / 128.0f, &s, &c);   // 2*pi*k*t/256
        g_basis[idx] = (ko & 1) ? -s : c;
        float a = (k == 0) ? (1.0f/NS) : (2.0f/NS);
        g_ibasisT[ko*NS + t] = (ko & 1) ? ((k == 0) ? 0.0f : -a*s) : a*c;
    }
    if (idx < NM*NC*NC) {
        int k = idx >> 12, r = idx & 4095, i = r >> 6, o = r & 63;
        int src = (i*NC + o)*NM + k;
        g_whT[0][idx] = whr[src];  g_whT[1][idx] = whi[src];
        g_wwT[0][idx] = wwr[src];  g_wwT[1][idx] = wwi[src];
    }
}

// ---------------- forward DFT over H: Xh[ko][w] = sum_h basis[h][ko] * x[h][w] ----------------
__global__ void __launch_bounds__(256) fdftH(const float* __restrict__ x) {
    __shared__ float sA[32][64];    // [h][ko]
    __shared__ float sB[32][128];   // [h][w]
    int slab = blockIdx.x;          // b*64 + i
    int w0 = blockIdx.y * 128;
    const float* xp = x + (size_t)slab * HW;
    int tx = threadIdx.x & 15, ty = threadIdx.x >> 4;
    u64 acc[4][4] = {};
    for (int hc = 0; hc < NS; hc += 32) {
        for (int idx = threadIdx.x; idx < 2048; idx += 256) {
            int r = idx >> 6, c = idx & 63;
            sA[r][c] = g_basis[(hc + r)*64 + c];
        }
        for (int idx = threadIdx.x; idx < 4096; idx += 256) {
            int r = idx >> 7, c = idx & 127;
            sB[r][c] = xp[(size_t)(hc + r)*NS + w0 + c];
        }
        __syncthreads();
        #pragma unroll 8
        for (int h = 0; h < 32; h++) {
            const float* ap = &sA[h][ty*4];
            float a0 = ap[0], a1 = ap[1], a2 = ap[2], a3 = ap[3];
            const u64* bp = (const u64*)&sB[h][tx*8];
            u64 b0 = bp[0], b1 = bp[1], b2 = bp[2], b3 = bp[3];
            u64 p;
            p = pk2(a0,a0); fma2(acc[0][0],p,b0); fma2(acc[0][1],p,b1); fma2(acc[0][2],p,b2); fma2(acc[0][3],p,b3);
            p = pk2(a1,a1); fma2(acc[1][0],p,b0); fma2(acc[1][1],p,b1); fma2(acc[1][2],p,b2); fma2(acc[1][3],p,b3);
            p = pk2(a2,a2); fma2(acc[2][0],p,b0); fma2(acc[2][1],p,b1); fma2(acc[2][2],p,b2); fma2(acc[2][3],p,b3);
            p = pk2(a3,a3); fma2(acc[3][0],p,b0); fma2(acc[3][1],p,b1); fma2(acc[3][2],p,b2); fma2(acc[3][3],p,b3);
        }
        __syncthreads();
    }
    float* dst = g_Xh + (size_t)slab * 64 * NS;
    #pragma unroll
    for (int j = 0; j < 4; j++) {
        u64* dp = (u64*)&dst[(ty*4 + j)*NS + w0 + tx*8];
        dp[0] = acc[j][0]; dp[1] = acc[j][1]; dp[2] = acc[j][2]; dp[3] = acc[j][3];
    }
}

// ---------------- forward DFT over W: Xw[ko][h] = sum_w basis[w][ko] * x[h][w] ----------------
__global__ void __launch_bounds__(256) fdftW(const float* __restrict__ x) {
    __shared__ float sA[32][64];      // [w][ko] direct
    __shared__ float sBt[32][132];    // [w][h] transposed (pad keeps rows 16B-aligned)
    int slab = blockIdx.x;
    int h0 = blockIdx.y * 128;
    const float* xp = x + (size_t)slab * HW;
    int tx = threadIdx.x & 15, ty = threadIdx.x >> 4;
    u64 acc[4][4] = {};
    for (int wc = 0; wc < NS; wc += 32) {
        for (int idx = threadIdx.x; idx < 2048; idx += 256) {
            int r = idx >> 6, c = idx & 63;
            sA[r][c] = g_basis[(wc + r)*64 + c];
        }
        for (int idx = threadIdx.x; idx < 4096; idx += 256) {
            int ww = idx & 31, hh = idx >> 5;     // coalesced global read along w
            sBt[ww][hh] = xp[(size_t)(h0 + hh)*NS + wc + ww];
        }
        __syncthreads();
        #pragma unroll 8
        for (int w = 0; w < 32; w++) {
            const float* ap = &sA[w][ty*4];
            float a0 = ap[0], a1 = ap[1], a2 = ap[2], a3 = ap[3];
            const u64* bp = (const u64*)&sBt[w][tx*8];
            u64 b0 = bp[0], b1 = bp[1], b2 = bp[2], b3 = bp[3];
            u64 p;
            p = pk2(a0,a0); fma2(acc[0][0],p,b0); fma2(acc[0][1],p,b1); fma2(acc[0][2],p,b2); fma2(acc[0][3],p,b3);
            p = pk2(a1,a1); fma2(acc[1][0],p,b0); fma2(acc[1][1],p,b1); fma2(acc[1][2],p,b2); fma2(acc[1][3],p,b3);
            p = pk2(a2,a2); fma2(acc[2][0],p,b0); fma2(acc[2][1],p,b1); fma2(acc[2][2],p,b2); fma2(acc[2][3],p,b3);
            p = pk2(a3,a3); fma2(acc[3][0],p,b0); fma2(acc[3][1],p,b1); fma2(acc[3][2],p,b2); fma2(acc[3][3],p,b3);
        }
        __syncthreads();
    }
    float* dst = g_Xw + (size_t)slab * 64 * NS;
    #pragma unroll
    for (int j = 0; j < 4; j++) {
        u64* dp = (u64*)&dst[(ty*4 + j)*NS + h0 + tx*8];
        dp[0] = acc[j][0]; dp[1] = acc[j][1]; dp[2] = acc[j][2]; dp[3] = acc[j][3];
    }
}

// ---------------- per-mode complex channel mix ----------------
__global__ void __launch_bounds__(256) mixK() {
    __shared__ float sWr[16][64], sWi[16][64], sXr[16][64], sXi[16][64];
    int br = blockIdx.z;
    const float* Xin = br ? g_Xw : g_Xh;
    const float* Wr  = br ? g_wwT[0] : g_whT[0];
    const float* Wi  = br ? g_wwT[1] : g_whT[1];
    float* Out       = br ? g_Ow : g_Oh;
    int b = blockIdx.x >> 5, k = blockIdx.x & 31;
    int c0 = blockIdx.y * 64;
    int tx = threadIdx.x & 15, ty = threadIdx.x >> 4;
    u64 accr[4][2] = {}, acci[4][2] = {};
    for (int ic = 0; ic < 64; ic += 16) {
        for (int idx = threadIdx.x; idx < 1024; idx += 256) {
            int i = idx >> 6, c = idx & 63;
            sWr[i][c] = Wr[(k*64 + ic + i)*64 + c];
            sWi[i][c] = Wi[(k*64 + ic + i)*64 + c];
            const float* xb = Xin + ((size_t)(b*64 + ic + i)*64 + 2*k)*NS + c0;
            sXr[i][c] = xb[c];
            sXi[i][c] = xb[NS + c];
        }
        __syncthreads();
        #pragma unroll 4
        for (int i = 0; i < 16; i++) {
            float ar[4], ai[4];
            #pragma unroll
            for (int j = 0; j < 4; j++) { ar[j] = sWr[i][ty*4+j]; ai[j] = sWi[i][ty*4+j]; }
            const u64* brp = (const u64*)&sXr[i][tx*4];
            const u64* bip = (const u64*)&sXi[i][tx*4];
            u64 br0 = brp[0], br1 = brp[1], bi0 = bip[0], bi1 = bip[1];
            #pragma unroll
            for (int j = 0; j < 4; j++) {
                u64 arp = pk2(ar[j], ar[j]);
                u64 aip = pk2(ai[j], ai[j]);
                u64 nap = pk2(-ai[j], -ai[j]);
                fma2(accr[j][0], arp, br0); fma2(accr[j][0], nap, bi0);
                fma2(accr[j][1], arp, br1); fma2(accr[j][1], nap, bi1);
                fma2(acci[j][0], arp, bi0); fma2(acci[j][0], aip, br0);
                fma2(acci[j][1], arp, bi1); fma2(acci[j][1], aip, br1);
            }
        }
        __syncthreads();
    }
    #pragma unroll
    for (int j = 0; j < 4; j++) {
        float* ob = Out + ((size_t)(b*64 + ty*4 + j)*64 + 2*k)*NS + c0 + tx*4;
        ((u64*)ob)[0] = accr[j][0]; ((u64*)ob)[1] = accr[j][1];
        ((u64*)(ob + NS))[0] = acci[j][0]; ((u64*)(ob + NS))[1] = acci[j][1];
    }
}

// ---------------- fused inverse DFTs: f[h][w] = invH(Oh) + invW(Ow) ----------------
__global__ void __launch_bounds__(256) invHW() {
    __shared__ float sAh[16][64];     // ibasisT[ko][h-tile]
    __shared__ float sAw[16][64];     // Ow[ko][h-tile]
    __shared__ float sBh[16][128];    // Oh[ko][w-tile]
    __shared__ float sBw[16][128];    // ibasisT[ko][w-tile]
    int slab = blockIdx.x;
    int h0 = (blockIdx.y >> 1) * 64, w0 = (blockIdx.y & 1) * 128;
    const float* Oh = g_Oh + (size_t)slab * 64 * NS;
    const float* Ow = g_Ow + (size_t)slab * 64 * NS;
    int tx = threadIdx.x & 15, ty = threadIdx.x >> 4;
    u64 acc[4][4] = {};
    for (int kc = 0; kc < 64; kc += 16) {
        for (int idx = threadIdx.x; idx < 1024; idx += 256) {
            int r = idx >> 6, c = idx & 63;
            sAh[r][c] = g_ibasisT[(kc + r)*NS + h0 + c];
            sAw[r][c] = Ow[(kc + r)*NS + h0 + c];
        }
        for (int idx = threadIdx.x; idx < 2048; idx += 256) {
            int r = idx >> 7, c = idx & 127;
            sBh[r][c] = Oh[(kc + r)*NS + w0 + c];
            sBw[r][c] = g_ibasisT[(kc + r)*NS + w0 + c];
        }
        __syncthreads();
        #pragma unroll 4
        for (int ko = 0; ko < 16; ko++) {
            float a1[4], a2[4];
            #pragma unroll
            for (int j = 0; j < 4; j++) { a1[j] = sAh[ko][ty*4+j]; a2[j] = sAw[ko][ty*4+j]; }
            const u64* b1p = (const u64*)&sBh[ko][tx*8];
            const u64* b2p = (const u64*)&sBw[ko][tx*8];
            u64 b10 = b1p[0], b11 = b1p[1], b12 = b1p[2], b13 = b1p[3];
            u64 b20 = b2p[0], b21 = b2p[1], b22 = b2p[2], b23 = b2p[3];
            #pragma unroll
            for (int j = 0; j < 4; j++) {
                u64 p1 = pk2(a1[j], a1[j]);
                u64 p2 = pk2(a2[j], a2[j]);
                fma2(acc[j][0], p1, b10); fma2(acc[j][0], p2, b20);
                fma2(acc[j][1], p1, b11); fma2(acc[j][1], p2, b21);
                fma2(acc[j][2], p1, b12); fma2(acc[j][2], p2, b22);
                fma2(acc[j][3], p1, b13); fma2(acc[j][3], p2, b23);
            }
        }
        __syncthreads();
    }
    float* fp = g_f + (size_t)slab * HW;
    #pragma unroll
    for (int j = 0; j < 4; j++) {
        u64* dp = (u64*)&fp[(size_t)(h0 + ty*4 + j)*NS + w0 + tx*8];
        dp[0] = acc[j][0]; dp[1] = acc[j][1]; dp[2] = acc[j][2]; dp[3] = acc[j][3];
    }
}

// ---------------- fused FFN: fc1 + relu + LN + fc2 + residual ----------------
__global__ void __launch_bounds__(256) ffnK(const float* __restrict__ x,
                     const float* __restrict__ w1, const float* __restrict__ b1,
                     const float* __restrict__ lng, const float* __restrict__ lnb,
                     const float* __restrict__ w2, const float* __restrict__ b2,
                     float* __restrict__ out) {
    __shared__ float sF[64*64];     // [c][px]
    __shared__ float sT[64*128];    // [px][feature]; later reused padded [o][px]
    int b = blockIdx.x >> 10;
    int p0 = (blockIdx.x & 1023) * 64;
    int tid = threadIdx.x;

    for (int idx = tid; idx < 4096; idx += 256) {
        int c = idx >> 6, px = idx & 63;
        sF[c*64 + px] = g_f[((size_t)(b*64 + c) << 16) + p0 + px];
    }
    __syncthreads();

    // stage 1: t1 = relu(f @ w1 + b1)
    {
        int tx = tid & 31, ty = tid >> 5;       // tx -> 4 outs (2 pairs), ty -> 8 px
        u64 acc[8][2] = {};
        for (int c = 0; c < 64; c++) {
            const u64* wp = (const u64*)&w1[c*128 + tx*4];
            u64 wa = wp[0], wb = wp[1];
            float4 f0 = *(const float4*)&sF[c*64 + ty*8];
            float4 f1 = *(const float4*)&sF[c*64 + ty*8 + 4];
            float fv[8] = {f0.x, f0.y, f0.z, f0.w, f1.x, f1.y, f1.z, f1.w};
            #pragma unroll
            for (int p = 0; p < 8; p++) {
                u64 fp_ = pk2(fv[p], fv[p]);
                fma2(acc[p][0], fp_, wa);
                fma2(acc[p][1], fp_, wb);
            }
        }
        float bb0 = b1[tx*4], bb1 = b1[tx*4+1], bb2 = b1[tx*4+2], bb3 = b1[tx*4+3];
        #pragma unroll
        for (int p = 0; p < 8; p++) {
            float v0, v1, v2, v3;
            up2(acc[p][0], v0, v1);
            up2(acc[p][1], v2, v3);
            float* tp = &sT[(ty*8 + p)*128 + tx*4];
            tp[0] = fmaxf(v0 + bb0, 0.0f);
            tp[1] = fmaxf(v1 + bb1, 0.0f);
            tp[2] = fmaxf(v2 + bb2, 0.0f);
            tp[3] = fmaxf(v3 + bb3, 0.0f);
        }
    }
    __syncthreads();

    // LayerNorm over 128 features; one warp handles 8 pixels
    {
        int wid = tid >> 5, lane = tid & 31;
        for (int p8 = 0; p8 < 8; p8++) {
            int px = wid*8 + p8;
            float v[4], s1 = 0.f, s2 = 0.f;
            #pragma unroll
            for (int j = 0; j < 4; j++) {
                v[j] = sT[px*128 + lane*4 + j];
                s1 += v[j]; s2 += v[j]*v[j];
            }
            #pragma unroll
            for (int o = 16; o > 0; o >>= 1) {
                s1 += __shfl_xor_sync(0xFFFFFFFFu, s1, o);
                s2 += __shfl_xor_sync(0xFFFFFFFFu, s2, o);
            }
            float mu  = s1 * (1.0f/128.0f);
            float var = s2 * (1.0f/128.0f) - mu*mu;
            float inv = rsqrtf(var + 1e-5f);
            #pragma unroll
            for (int j = 0; j < 4; j++)
                sT[px*128 + lane*4 + j] =
                    (v[j] - mu) * inv * lng[lane*4 + j] + lnb[lane*4 + j];
        }
    }
    __syncthreads();

    // stage 2: t2 = t1n @ w2
    u64 acc2[4][2] = {};
    {
        int tx = tid & 15, ty = tid >> 4;       // tx -> 4 outs (2 pairs), ty -> 4 px
        for (int kk = 0; kk < 128; kk += 4) {
            float4 t4[4];
            #pragma unroll
            for (int d = 0; d < 4; d++)
                t4[d] = *(const float4*)&sT[(ty*4 + d)*128 + kk];
            #pragma unroll
            for (int q = 0; q < 4; q++) {
                const u64* wp = (const u64*)&w2[(kk + q)*64 + tx*4];
                u64 wa = wp[0], wb = wp[1];
                #pragma unroll
                for (int d = 0; d < 4; d++) {
                    float t = (q == 0) ? t4[d].x : (q == 1) ? t4[d].y : (q == 2) ? t4[d].z : t4[d].w;
                    u64 tp = pk2(t, t);
                    fma2(acc2[d][0], tp, wa);
                    fma2(acc2[d][1], tp, wb);
                }
            }
        }
    }
    __syncthreads();
    // stash t2 into sT as padded [o][px] for coalesced writeout
    {
        int tx = tid & 15, ty = tid >> 4;
        #pragma unroll
        for (int d = 0; d < 4; d++) {
            float v0, v1, v2, v3;
            up2(acc2[d][0], v0, v1);
            up2(acc2[d][1], v2, v3);
            sT[(tx*4 + 0)*65 + ty*4 + d] = v0;
            sT[(tx*4 + 1)*65 + ty*4 + d] = v1;
            sT[(tx*4 + 2)*65 + ty*4 + d] = v2;
            sT[(tx*4 + 3)*65 + ty*4 + d] = v3;
        }
    }
    __syncthreads();
    for (int idx = tid; idx < 4096; idx += 256) {
        int o = idx >> 6, px = idx & 63;
        size_t gg = ((size_t)(b*64 + o) << 16) + p0 + px;
        out[gg] = sT[o*65 + px] + b2[o] + x[gg];
    }
}

// ---------------- launch ----------------
extern "C" void kernel_launch(void* const* d_in, const int* in_sizes, int n_in,
                              void* d_out, int out_size) {
    const float* x    = (const float*)d_in[0];
    const float* whr  = (const float*)d_in[1];
    const float* whi  = (const float*)d_in[2];
    const float* wwr  = (const float*)d_in[3];
    const float* wwi  = (const float*)d_in[4];
    const float* fc1w = (const float*)d_in[5];
    const float* fc1b = (const float*)d_in[6];
    const float* lng  = (const float*)d_in[7];
    const float* lnb  = (const float*)d_in[8];
    const float* fc2w = (const float*)d_in[9];
    const float* fc2b = (const float*)d_in[10];
    float* out = (float*)d_out;

    initK<<<512, 256>>>(whr, whi, wwr, wwi);
    fdftH<<<dim3(512, 2), 256>>>(x);
    fdftW<<<dim3(512, 2), 256>>>(x);
    mixK<<<dim3(256, 4, 2), 256>>>();
    invHW<<<dim3(512, 8), 256>>>();
    ffnK<<<8192, 256>>>(x, fc1w, fc1b, lng, lnb, fc2w, fc2b, out);
}

// round 7
// speedup vs baseline: 1.1486x; 1.0853x over previous
#include <cuda_runtime.h>
#include <math.h>

#define NB 8
#define NC 64
#define NS 256
#define NM 32
#define HW (NS*NS)

typedef unsigned long long u64;
typedef unsigned int u32;

__device__ __forceinline__ u64 pk2(float lo, float hi) {
    u64 r; asm("mov.b64 %0,{%1,%2};" : "=l"(r) : "f"(lo), "f"(hi)); return r;
}
__device__ __forceinline__ void fma2(u64 &d, u64 a, u64 b) {
    asm("fma.rn.f32x2 %0,%1,%2,%0;" : "+l"(d) : "l"(a), "l"(b));
}
__device__ __forceinline__ u32 tf32b(float f) {
    u32 u; asm("cvt.rna.tf32.f32 %0, %1;" : "=r"(u) : "f"(f)); return u;
}
__device__ __forceinline__ void mma816(float* d, const u32* a, const u32* b) {
    asm volatile("mma.sync.aligned.m16n8k8.row.col.f32.tf32.tf32.f32 "
        "{%0,%1,%2,%3}, {%4,%5,%6,%7}, {%8,%9}, {%0,%1,%2,%3};"
        : "+f"(d[0]), "+f"(d[1]), "+f"(d[2]), "+f"(d[3])
        : "r"(a[0]), "r"(a[1]), "r"(a[2]), "r"(a[3]), "r"(b[0]), "r"(b[1]));
}

// ---------------- static device scratch (no allocation) ----------------
__device__ float g_basis[NS*64];       // fwd DFT [t][ko]: even=cos, odd=-sin
__device__ float g_ibasisT[64*NS];     // inv DFT transposed [ko][t]
__device__ float g_whT[2][NM*NC*NC];
__device__ float g_wwT[2][NM*NC*NC];
__device__ float g_Xh[(size_t)NB*NC*64*NS];
__device__ float g_Xw[(size_t)NB*NC*64*NS];
__device__ float g_Oh[(size_t)NB*NC*64*NS];
__device__ float g_Ow[(size_t)NB*NC*64*NS];
__device__ float g_f [(size_t)NB*NC*HW];

// ---------------- init ----------------
__global__ void initK(const float* __restrict__ whr, const float* __restrict__ whi,
                      const float* __restrict__ wwr, const float* __restrict__ wwi) {
    int idx = blockIdx.x * 256 + threadIdx.x;
    if (idx < NS*64) {
        int t = idx >> 6, ko = idx & 63, k = ko >> 1;
        float s, c;
        sincospif((float)((k * t) & 255) / 128.0f, &s, &c);
        g_basis[idx] = (ko & 1) ? -s : c;
        float a = (k == 0) ? (1.0f/NS) : (2.0f/NS);
        g_ibasisT[ko*NS + t] = (ko & 1) ? ((k == 0) ? 0.0f : -a*s) : a*c;
    }
    if (idx < NM*NC*NC) {
        int k = idx >> 12, r = idx & 4095, i = r >> 6, o = r & 63;
        int src = (i*NC + o)*NM + k;
        g_whT[0][idx] = whr[src];  g_whT[1][idx] = whi[src];
        g_wwT[0][idx] = wwr[src];  g_wwT[1][idx] = wwi[src];
    }
}

// ---------------- forward DFT over H ----------------
__global__ void __launch_bounds__(256) fdftH(const float* __restrict__ x) {
    __shared__ float sA[32][64];
    __shared__ float sB[32][128];
    int slab = blockIdx.x;
    int w0 = blockIdx.y * 128;
    const float* xp = x + (size_t)slab * HW;
    int tx = threadIdx.x & 15, ty = threadIdx.x >> 4;
    u64 acc[4][4] = {};
    for (int hc = 0; hc < NS; hc += 32) {
        for (int idx = threadIdx.x; idx < 2048; idx += 256) {
            int r = idx >> 6, c = idx & 63;
            sA[r][c] = g_basis[(hc + r)*64 + c];
        }
        for (int idx = threadIdx.x; idx < 4096; idx += 256) {
            int r = idx >> 7, c = idx & 127;
            sB[r][c] = xp[(size_t)(hc + r)*NS + w0 + c];
        }
        __syncthreads();
        #pragma unroll 8
        for (int h = 0; h < 32; h++) {
            const float* ap = &sA[h][ty*4];
            float a0 = ap[0], a1 = ap[1], a2 = ap[2], a3 = ap[3];
            const u64* bp = (const u64*)&sB[h][tx*8];
            u64 b0 = bp[0], b1 = bp[1], b2 = bp[2], b3 = bp[3];
            u64 p;
            p = pk2(a0,a0); fma2(acc[0][0],p,b0); fma2(acc[0][1],p,b1); fma2(acc[0][2],p,b2); fma2(acc[0][3],p,b3);
            p = pk2(a1,a1); fma2(acc[1][0],p,b0); fma2(acc[1][1],p,b1); fma2(acc[1][2],p,b2); fma2(acc[1][3],p,b3);
            p = pk2(a2,a2); fma2(acc[2][0],p,b0); fma2(acc[2][1],p,b1); fma2(acc[2][2],p,b2); fma2(acc[2][3],p,b3);
            p = pk2(a3,a3); fma2(acc[3][0],p,b0); fma2(acc[3][1],p,b1); fma2(acc[3][2],p,b2); fma2(acc[3][3],p,b3);
        }
        __syncthreads();
    }
    float* dst = g_Xh + (size_t)slab * 64 * NS;
    #pragma unroll
    for (int j = 0; j < 4; j++) {
        u64* dp = (u64*)&dst[(ty*4 + j)*NS + w0 + tx*8];
        dp[0] = acc[j][0]; dp[1] = acc[j][1]; dp[2] = acc[j][2]; dp[3] = acc[j][3];
    }
}

// ---------------- forward DFT over W ----------------
__global__ void __launch_bounds__(256) fdftW(const float* __restrict__ x) {
    __shared__ float sA[32][64];
    __shared__ float sBt[32][132];
    int slab = blockIdx.x;
    int h0 = blockIdx.y * 128;
    const float* xp = x + (size_t)slab * HW;
    int tx = threadIdx.x & 15, ty = threadIdx.x >> 4;
    u64 acc[4][4] = {};
    for (int wc = 0; wc < NS; wc += 32) {
        for (int idx = threadIdx.x; idx < 2048; idx += 256) {
            int r = idx >> 6, c = idx & 63;
            sA[r][c] = g_basis[(wc + r)*64 + c];
        }
        for (int idx = threadIdx.x; idx < 4096; idx += 256) {
            int ww = idx & 31, hh = idx >> 5;
            sBt[ww][hh] = xp[(size_t)(h0 + hh)*NS + wc + ww];
        }
        __syncthreads();
        #pragma unroll 8
        for (int w = 0; w < 32; w++) {
            const float* ap = &sA[w][ty*4];
            float a0 = ap[0], a1 = ap[1], a2 = ap[2], a3 = ap[3];
            const u64* bp = (const u64*)&sBt[w][tx*8];
            u64 b0 = bp[0], b1 = bp[1], b2 = bp[2], b3 = bp[3];
            u64 p;
            p = pk2(a0,a0); fma2(acc[0][0],p,b0); fma2(acc[0][1],p,b1); fma2(acc[0][2],p,b2); fma2(acc[0][3],p,b3);
            p = pk2(a1,a1); fma2(acc[1][0],p,b0); fma2(acc[1][1],p,b1); fma2(acc[1][2],p,b2); fma2(acc[1][3],p,b3);
            p = pk2(a2,a2); fma2(acc[2][0],p,b0); fma2(acc[2][1],p,b1); fma2(acc[2][2],p,b2); fma2(acc[2][3],p,b3);
            p = pk2(a3,a3); fma2(acc[3][0],p,b0); fma2(acc[3][1],p,b1); fma2(acc[3][2],p,b2); fma2(acc[3][3],p,b3);
        }
        __syncthreads();
    }
    float* dst = g_Xw + (size_t)slab * 64 * NS;
    #pragma unroll
    for (int j = 0; j < 4; j++) {
        u64* dp = (u64*)&dst[(ty*4 + j)*NS + h0 + tx*8];
        dp[0] = acc[j][0]; dp[1] = acc[j][1]; dp[2] = acc[j][2]; dp[3] = acc[j][3];
    }
}

// ---------------- per-mode complex channel mix ----------------
__global__ void __launch_bounds__(256) mixK() {
    __shared__ float sWr[16][64], sWi[16][64], sXr[16][64], sXi[16][64];
    int br = blockIdx.z;
    const float* Xin = br ? g_Xw : g_Xh;
    const float* Wr  = br ? g_wwT[0] : g_whT[0];
    const float* Wi  = br ? g_wwT[1] : g_whT[1];
    float* Out       = br ? g_Ow : g_Oh;
    int b = blockIdx.x >> 5, k = blockIdx.x & 31;
    int c0 = blockIdx.y * 64;
    int tx = threadIdx.x & 15, ty = threadIdx.x >> 4;
    u64 accr[4][2] = {}, acci[4][2] = {};
    for (int ic = 0; ic < 64; ic += 16) {
        for (int idx = threadIdx.x; idx < 1024; idx += 256) {
            int i = idx >> 6, c = idx & 63;
            sWr[i][c] = Wr[(k*64 + ic + i)*64 + c];
            sWi[i][c] = Wi[(k*64 + ic + i)*64 + c];
            const float* xb = Xin + ((size_t)(b*64 + ic + i)*64 + 2*k)*NS + c0;
            sXr[i][c] = xb[c];
            sXi[i][c] = xb[NS + c];
        }
        __syncthreads();
        #pragma unroll 4
        for (int i = 0; i < 16; i++) {
            float ar[4], ai[4];
            #pragma unroll
            for (int j = 0; j < 4; j++) { ar[j] = sWr[i][ty*4+j]; ai[j] = sWi[i][ty*4+j]; }
            const u64* brp = (const u64*)&sXr[i][tx*4];
            const u64* bip = (const u64*)&sXi[i][tx*4];
            u64 br0 = brp[0], br1 = brp[1], bi0 = bip[0], bi1 = bip[1];
            #pragma unroll
            for (int j = 0; j < 4; j++) {
                u64 arp = pk2(ar[j], ar[j]);
                u64 aip = pk2(ai[j], ai[j]);
                u64 nap = pk2(-ai[j], -ai[j]);
                fma2(accr[j][0], arp, br0); fma2(accr[j][0], nap, bi0);
                fma2(accr[j][1], arp, br1); fma2(accr[j][1], nap, bi1);
                fma2(acci[j][0], arp, bi0); fma2(acci[j][0], aip, br0);
                fma2(acci[j][1], arp, bi1); fma2(acci[j][1], aip, br1);
            }
        }
        __syncthreads();
    }
    #pragma unroll
    for (int j = 0; j < 4; j++) {
        float* ob = Out + ((size_t)(b*64 + ty*4 + j)*64 + 2*k)*NS + c0 + tx*4;
        ((u64*)ob)[0] = accr[j][0]; ((u64*)ob)[1] = accr[j][1];
        ((u64*)(ob + NS))[0] = acci[j][0]; ((u64*)(ob + NS))[1] = acci[j][1];
    }
}

// ---------------- fused inverse DFTs ----------------
__global__ void __launch_bounds__(256) invHW() {
    __shared__ float sAh[16][64];
    __shared__ float sAw[16][64];
    __shared__ float sBh[16][128];
    __shared__ float sBw[16][128];
    int slab = blockIdx.x;
    int h0 = (blockIdx.y >> 1) * 64, w0 = (blockIdx.y & 1) * 128;
    const float* Oh = g_Oh + (size_t)slab * 64 * NS;
    const float* Ow = g_Ow + (size_t)slab * 64 * NS;
    int tx = threadIdx.x & 15, ty = threadIdx.x >> 4;
    u64 acc[4][4] = {};
    for (int kc = 0; kc < 64; kc += 16) {
        for (int idx = threadIdx.x; idx < 1024; idx += 256) {
            int r = idx >> 6, c = idx & 63;
            sAh[r][c] = g_ibasisT[(kc + r)*NS + h0 + c];
            sAw[r][c] = Ow[(kc + r)*NS + h0 + c];
        }
        for (int idx = threadIdx.x; idx < 2048; idx += 256) {
            int r = idx >> 7, c = idx & 127;
            sBh[r][c] = Oh[(kc + r)*NS + w0 + c];
            sBw[r][c] = g_ibasisT[(kc + r)*NS + w0 + c];
        }
        __syncthreads();
        #pragma unroll 4
        for (int ko = 0; ko < 16; ko++) {
            float a1[4], a2[4];
            #pragma unroll
            for (int j = 0; j < 4; j++) { a1[j] = sAh[ko][ty*4+j]; a2[j] = sAw[ko][ty*4+j]; }
            const u64* b1p = (const u64*)&sBh[ko][tx*8];
            const u64* b2p = (const u64*)&sBw[ko][tx*8];
            u64 b10 = b1p[0], b11 = b1p[1], b12 = b1p[2], b13 = b1p[3];
            u64 b20 = b2p[0], b21 = b2p[1], b22 = b2p[2], b23 = b2p[3];
            #pragma unroll
            for (int j = 0; j < 4; j++) {
                u64 p1 = pk2(a1[j], a1[j]);
                u64 p2 = pk2(a2[j], a2[j]);
                fma2(acc[j][0], p1, b10); fma2(acc[j][0], p2, b20);
                fma2(acc[j][1], p1, b11); fma2(acc[j][1], p2, b21);
                fma2(acc[j][2], p1, b12); fma2(acc[j][2], p2, b22);
                fma2(acc[j][3], p1, b13); fma2(acc[j][3], p2, b23);
            }
        }
        __syncthreads();
    }
    float* fp = g_f + (size_t)slab * HW;
    #pragma unroll
    for (int j = 0; j < 4; j++) {
        u64* dp = (u64*)&fp[(size_t)(h0 + ty*4 + j)*NS + w0 + tx*8];
        dp[0] = acc[j][0]; dp[1] = acc[j][1]; dp[2] = acc[j][2]; dp[3] = acc[j][3];
    }
}

// ---------------- mma.sync tf32 FFN ----------------
// SMEM (bytes): 0 vecs (b1[128] lng[128] lnb[128] b2[64] = 1792, pad 2048)
// | 2048 sA [64px][68] f32 (17408) | 19456 sT [64px][132] f32 (33792)
// | 53248 sW: B1 [64][136] (34816) / B2 [128][72] (36864)  -> total 90112
#define FFN_SMEM 90112
#define OFF_SA 2048
#define OFF_T1 19456
#define OFF_WB 53248

__global__ void __launch_bounds__(256) ffnM(const float* __restrict__ x,
        const float* __restrict__ w1, const float* __restrict__ b1,
        const float* __restrict__ lng, const float* __restrict__ lnb,
        const float* __restrict__ w2, const float* __restrict__ b2,
        float* __restrict__ out) {
    extern __shared__ __align__(16) char smem[];
    float* sVec = (float*)smem;
    float* sA = (float*)(smem + OFF_SA);
    float* sT = (float*)(smem + OFF_T1);
    float* sW = (float*)(smem + OFF_WB);
    int tid = threadIdx.x, lane = tid & 31, w = tid >> 5;
    int b  = blockIdx.x >> 10;
    int p0 = (blockIdx.x & 1023) * 64;

    if (tid < 128) { sVec[tid] = b1[tid]; sVec[128+tid] = lng[tid]; sVec[256+tid] = lnb[tid]; }
    if (tid < 64) sVec[384+tid] = b2[tid];
    for (int i = tid; i < 8192; i += 256) {            // B1 = w1 [c][j] tf32
        int c = i >> 7, j = i & 127;
        sW[c*136 + j] = __uint_as_float(tf32b(w1[i]));
    }
    for (int i = tid; i < 4096; i += 256) {            // sA = f tile [px][c] tf32
        int c = i >> 6, px = i & 63;
        sA[px*68 + c] = __uint_as_float(tf32b(g_f[((size_t)(b*64 + c) << 16) + p0 + px]));
    }
    __syncthreads();

    int warpM = w & 1, warpN = w >> 1;
    int g = lane >> 2, tig = lane & 3;

    // GEMM1: [64px x 128j] = sA[64x64] @ B1[64x128]
    float acc[2][4][4] = {};
    #pragma unroll
    for (int ks = 0; ks < 8; ks++) {
        int k0 = ks * 8;
        u32 afr[2][4];
        #pragma unroll
        for (int mt = 0; mt < 2; mt++) {
            const float* ap = sA + (warpM*32 + mt*16)*68 + k0;
            afr[mt][0] = __float_as_uint(ap[g*68 + tig]);
            afr[mt][1] = __float_as_uint(ap[(g+8)*68 + tig]);
            afr[mt][2] = __float_as_uint(ap[g*68 + tig + 4]);
            afr[mt][3] = __float_as_uint(ap[(g+8)*68 + tig + 4]);
        }
        #pragma unroll
        for (int nt = 0; nt < 4; nt++) {
            const float* bp = sW + k0*136 + warpN*32 + nt*8;
            u32 bfr[2];
            bfr[0] = __float_as_uint(bp[tig*136 + g]);
            bfr[1] = __float_as_uint(bp[(tig+4)*136 + g]);
            mma816(acc[0][nt], afr[0], bfr);
            mma816(acc[1][nt], afr[1], bfr);
        }
    }
    // epilogue1: bias + relu -> sT [px][132]
    #pragma unroll
    for (int mt = 0; mt < 2; mt++) {
        int r0 = warpM*32 + mt*16 + g;
        #pragma unroll
        for (int nt = 0; nt < 4; nt++) {
            int cb = warpN*32 + nt*8 + 2*tig;
            float bb0 = sVec[cb], bb1 = sVec[cb+1];
            sT[r0*132 + cb]     = fmaxf(acc[mt][nt][0] + bb0, 0.f);
            sT[r0*132 + cb + 1] = fmaxf(acc[mt][nt][1] + bb1, 0.f);
            sT[(r0+8)*132 + cb]     = fmaxf(acc[mt][nt][2] + bb0, 0.f);
            sT[(r0+8)*132 + cb + 1] = fmaxf(acc[mt][nt][3] + bb1, 0.f);
        }
    }
    __syncthreads();

    // LayerNorm: warp w -> pixels w*8 .. w*8+7; write back tf32
    for (int p8 = 0; p8 < 8; p8++) {
        int px = w*8 + p8;
        float4 v = *(float4*)&sT[px*132 + lane*4];
        float s1 = v.x + v.y + v.z + v.w;
        float s2 = v.x*v.x + v.y*v.y + v.z*v.z + v.w*v.w;
        #pragma unroll
        for (int o = 16; o > 0; o >>= 1) {
            s1 += __shfl_xor_sync(0xFFFFFFFFu, s1, o);
            s2 += __shfl_xor_sync(0xFFFFFFFFu, s2, o);
        }
        float mu  = s1 * (1.0f/128.0f);
        float var = s2 * (1.0f/128.0f) - mu*mu;
        float inv = rsqrtf(var + 1e-5f);
        float4 gm = *(float4*)&sVec[128 + lane*4];
        float4 bt = *(float4*)&sVec[256 + lane*4];
        uint4 q;
        q.x = tf32b((v.x - mu)*inv*gm.x + bt.x);
        q.y = tf32b((v.y - mu)*inv*gm.y + bt.y);
        q.z = tf32b((v.z - mu)*inv*gm.z + bt.z);
        q.w = tf32b((v.w - mu)*inv*gm.w + bt.w);
        *(uint4*)&sT[px*132 + lane*4] = q;
    }
    __syncthreads();

    // B2 = w2 [j][o] tf32 (overwrites B1 buffer)
    for (int i = tid; i < 8192; i += 256) {
        int j = i >> 6, o = i & 63;
        sW[j*72 + o] = __uint_as_float(tf32b(w2[i]));
    }
    __syncthreads();

    // GEMM2: [64px x 64o] = sT[64x128] @ B2[128x64]
    float acc2[2][2][4] = {};
    #pragma unroll
    for (int ks = 0; ks < 16; ks++) {
        int k0 = ks * 8;
        u32 afr[2][4];
        #pragma unroll
        for (int mt = 0; mt < 2; mt++) {
            const float* ap = sT + (warpM*32 + mt*16)*132 + k0;
            afr[mt][0] = __float_as_uint(ap[g*132 + tig]);
            afr[mt][1] = __float_as_uint(ap[(g+8)*132 + tig]);
            afr[mt][2] = __float_as_uint(ap[g*132 + tig + 4]);
            afr[mt][3] = __float_as_uint(ap[(g+8)*132 + tig + 4]);
        }
        #pragma unroll
        for (int nt = 0; nt < 2; nt++) {
            const float* bp = sW + k0*72 + warpN*16 + nt*8;
            u32 bfr[2];
            bfr[0] = __float_as_uint(bp[tig*72 + g]);
            bfr[1] = __float_as_uint(bp[(tig+4)*72 + g]);
            mma816(acc2[0][nt], afr[0], bfr);
            mma816(acc2[1][nt], afr[1], bfr);
        }
    }
    // epilogue2: +b2 into transposed sO [o][68 px] (reuse sA region)
    float* sO = sA;
    #pragma unroll
    for (int mt = 0; mt < 2; mt++) {
        int r0 = warpM*32 + mt*16 + g;
        #pragma unroll
        for (int nt = 0; nt < 2; nt++) {
            int ob = warpN*16 + nt*8 + 2*tig;
            float bb0 = sVec[384 + ob], bb1 = sVec[384 + ob + 1];
            sO[ob*68 + r0]       = acc2[mt][nt][0] + bb0;
            sO[(ob+1)*68 + r0]   = acc2[mt][nt][1] + bb1;
            sO[ob*68 + r0 + 8]   = acc2[mt][nt][2] + bb0;
            sO[(ob+1)*68 + r0+8] = acc2[mt][nt][3] + bb1;
        }
    }
    __syncthreads();
    // residual + store
    for (int i = tid; i < 4096; i += 256) {
        int o = i >> 6, px = i & 63;
        size_t gg = ((size_t)(b*64 + o) << 16) + p0 + px;
        out[gg] = sO[o*68 + px] + x[gg];
    }
}

// ---------------- launch ----------------
extern "C" void kernel_launch(void* const* d_in, const int* in_sizes, int n_in,
                              void* d_out, int out_size) {
    const float* x    = (const float*)d_in[0];
    const float* whr  = (const float*)d_in[1];
    const float* whi  = (const float*)d_in[2];
    const float* wwr  = (const float*)d_in[3];
    const float* wwi  = (const float*)d_in[4];
    const float* fc1w = (const float*)d_in[5];
    const float* fc1b = (const float*)d_in[6];
    const float* lng  = (const float*)d_in[7];
    const float* lnb  = (const float*)d_in[8];
    const float* fc2w = (const float*)d_in[9];
    const float* fc2b = (const float*)d_in[10];
    float* out = (float*)d_out;

    cudaFuncSetAttribute(ffnM, cudaFuncAttributeMaxDynamicSharedMemorySize, FFN_SMEM);

    initK<<<512, 256>>>(whr, whi, wwr, wwi);
    fdftH<<<dim3(512, 2), 256>>>(x);
    fdftW<<<dim3(512, 2), 256>>>(x);
    mixK<<<dim3(256, 4, 2), 256>>>();
    invHW<<<dim3(512, 8), 256>>>();
    ffnM<<<8192, 256, FFN_SMEM>>>(x, fc1w, fc1b, lng, lnb, fc2w, fc2b, out);
}

// round 9
// speedup vs baseline: 1.4915x; 1.2985x over previous
#include <cuda_runtime.h>
#include <math.h>

#define NB 8
#define NC 64
#define NS 256
#define NM 32
#define HW (NS*NS)

typedef unsigned long long u64;
typedef unsigned int u32;

__device__ __forceinline__ u32 tf32b(float f) {
    u32 u; asm("cvt.rna.tf32.f32 %0, %1;" : "=r"(u) : "f"(f)); return u;
}
__device__ __forceinline__ float stf(float f) { return __uint_as_float(tf32b(f)); }
__device__ __forceinline__ void mma816(float* d, const u32* a, const u32* b) {
    asm volatile("mma.sync.aligned.m16n8k8.row.col.f32.tf32.tf32.f32 "
        "{%0,%1,%2,%3}, {%4,%5,%6,%7}, {%8,%9}, {%0,%1,%2,%3};"
        : "+f"(d[0]), "+f"(d[1]), "+f"(d[2]), "+f"(d[3])
        : "r"(a[0]), "r"(a[1]), "r"(a[2]), "r"(a[3]), "r"(b[0]), "r"(b[1]));
}

// ---------------- static device scratch ----------------
__device__ float g_basisT[64*NS];      // fwd DFT [ko][t] tf32-rounded (even=cos, odd=-sin)
__device__ float g_ibasis[NS*64];      // inv DFT [t][ko] tf32-rounded (irfft weights folded)
__device__ float g_ibasisT[64*NS];     // inv DFT [ko][t] tf32-rounded
__device__ float g_whA[2][NM*NC*NC];   // [re/im][k][o][i] tf32-rounded
__device__ float g_wwA[2][NM*NC*NC];
__device__ float g_Xh[(size_t)NB*NC*64*NS];   // [b][i][ko][w]
__device__ float g_Xw[(size_t)NB*NC*64*NS];   // [b][i][ko][h]
__device__ float g_Oh[(size_t)NB*NC*64*NS];   // [b][o][ko][w]
__device__ float g_Ow[(size_t)NB*NC*64*NS];   // [b][o][ko][h]
__device__ float g_f [(size_t)NB*NC*HW];

// ---------------- init ----------------
__global__ void initK(const float* __restrict__ whr, const float* __restrict__ whi,
                      const float* __restrict__ wwr, const float* __restrict__ wwi) {
    int idx = blockIdx.x * 256 + threadIdx.x;      // covers 131072
    if (idx < NS*64) {
        int t = idx >> 6, ko = idx & 63, k = ko >> 1;
        float s, c;
        sincospif((float)((k * t) & 255) / 128.0f, &s, &c);
        g_basisT[ko*NS + t] = stf((ko & 1) ? -s : c);
        float a = (k == 0) ? (1.0f/NS) : (2.0f/NS);
        float iv = (ko & 1) ? ((k == 0) ? 0.0f : -a*s) : a*c;
        g_ibasis[t*64 + ko]  = stf(iv);
        g_ibasisT[ko*NS + t] = stf(iv);
    }
    if (idx < NM*NC*NC) {
        int k = idx >> 12, r = idx & 4095, o = r >> 6, i = r & 63;
        int src = (i*NC + o)*NM + k;
        g_whA[0][idx] = stf(whr[src]);  g_whA[1][idx] = stf(whi[src]);
        g_wwA[0][idx] = stf(wwr[src]);  g_wwA[1][idx] = stf(wwi[src]);
    }
}

// ---------------- forward DFT over H (mma): Xh[ko][w] = basisT[ko][h] @ x[h][w] ----------------
// dyn smem: sA 64*68 f32 (17408 B) | sB 64*132 f32 (33792 B) => 51200 B
#define FDH_SMEM 51200
__global__ void __launch_bounds__(256) fdftHm(const float* __restrict__ x) {
    extern __shared__ __align__(16) char smem[];
    float* sA = (float*)smem;
    float* sB = (float*)(smem + 17408);
    int slab = blockIdx.x;
    int w0 = blockIdx.y * 128;
    const float* xp = x + (size_t)slab * HW;
    int tid = threadIdx.x, lane = tid & 31, w = tid >> 5;
    int g = lane >> 2, tig = lane & 3;
    int warpM = w & 1, warpN = w >> 1;     // 2 x 4
    float acc[2][4][4] = {};
    for (int hc = 0; hc < NS; hc += 64) {
        for (int idx = tid; idx < 4096; idx += 256) {
            int ko = idx >> 6, hh = idx & 63;
            sA[ko*68 + hh] = g_basisT[ko*NS + hc + hh];
        }
        for (int idx = tid; idx < 8192; idx += 256) {
            int hh = idx >> 7, ww = idx & 127;
            sB[hh*132 + ww] = stf(xp[(size_t)(hc + hh)*NS + w0 + ww]);
        }
        __syncthreads();
        #pragma unroll
        for (int ks = 0; ks < 8; ks++) {
            int k0 = ks * 8;
            u32 af[2][4];
            #pragma unroll
            for (int mt = 0; mt < 2; mt++) {
                int r0 = warpM*32 + mt*16;
                af[mt][0] = __float_as_uint(sA[(r0+g)*68 + k0 + tig]);
                af[mt][1] = __float_as_uint(sA[(r0+g+8)*68 + k0 + tig]);
                af[mt][2] = __float_as_uint(sA[(r0+g)*68 + k0 + tig + 4]);
                af[mt][3] = __float_as_uint(sA[(r0+g+8)*68 + k0 + tig + 4]);
            }
            #pragma unroll
            for (int nt = 0; nt < 4; nt++) {
                int n0 = warpN*32 + nt*8;
                u32 bf[2];
                bf[0] = __float_as_uint(sB[(k0+tig)*132 + n0 + g]);
                bf[1] = __float_as_uint(sB[(k0+tig+4)*132 + n0 + g]);
                mma816(acc[0][nt], af[0], bf);
                mma816(acc[1][nt], af[1], bf);
            }
        }
        __syncthreads();
    }
    float* dst = g_Xh + (size_t)slab * 64 * NS;
    #pragma unroll
    for (int mt = 0; mt < 2; mt++) {
        int row = warpM*32 + mt*16 + g;
        #pragma unroll
        for (int nt = 0; nt < 4; nt++) {
            int col = w0 + warpN*32 + nt*8 + 2*tig;
            *(float2*)&dst[row*NS + col]     = make_float2(acc[mt][nt][0], acc[mt][nt][1]);
            *(float2*)&dst[(row+8)*NS + col] = make_float2(acc[mt][nt][2], acc[mt][nt][3]);
        }
    }
}

// ---------------- forward DFT over W (mma): Xw[ko][h] = basisT[ko][w] @ xT[w][h] ----------------
// dyn smem: sA 64*68 f32 (17408 B) | sB 64*133 f32 (34048 B) => 51456 B
#define FDW_SMEM 51456
__global__ void __launch_bounds__(256) fdftWm(const float* __restrict__ x) {
    extern __shared__ __align__(16) char smem[];
    float* sA = (float*)smem;
    float* sB = (float*)(smem + 17408);
    int slab = blockIdx.x;
    int h0 = blockIdx.y * 128;
    const float* xp = x + (size_t)slab * HW;
    int tid = threadIdx.x, lane = tid & 31, w = tid >> 5;
    int g = lane >> 2, tig = lane & 3;
    int warpM = w & 1, warpN = w >> 1;
    float acc[2][4][4] = {};
    for (int wc = 0; wc < NS; wc += 64) {
        for (int idx = tid; idx < 4096; idx += 256) {
            int ko = idx >> 6, ww = idx & 63;
            sA[ko*68 + ww] = g_basisT[ko*NS + wc + ww];
        }
        for (int idx = tid; idx < 8192; idx += 256) {
            int hh = idx >> 6, ww = idx & 63;
            sB[ww*133 + hh] = stf(xp[(size_t)(h0 + hh)*NS + wc + ww]);
        }
        __syncthreads();
        #pragma unroll
        for (int ks = 0; ks < 8; ks++) {
            int k0 = ks * 8;
            u32 af[2][4];
            #pragma unroll
            for (int mt = 0; mt < 2; mt++) {
                int r0 = warpM*32 + mt*16;
                af[mt][0] = __float_as_uint(sA[(r0+g)*68 + k0 + tig]);
                af[mt][1] = __float_as_uint(sA[(r0+g+8)*68 + k0 + tig]);
                af[mt][2] = __float_as_uint(sA[(r0+g)*68 + k0 + tig + 4]);
                af[mt][3] = __float_as_uint(sA[(r0+g+8)*68 + k0 + tig + 4]);
            }
            #pragma unroll
            for (int nt = 0; nt < 4; nt++) {
                int n0 = warpN*32 + nt*8;
                u32 bf[2];
                bf[0] = __float_as_uint(sB[(k0+tig)*133 + n0 + g]);
                bf[1] = __float_as_uint(sB[(k0+tig+4)*133 + n0 + g]);
                mma816(acc[0][nt], af[0], bf);
                mma816(acc[1][nt], af[1], bf);
            }
        }
        __syncthreads();
    }
    float* dst = g_Xw + (size_t)slab * 64 * NS;
    #pragma unroll
    for (int mt = 0; mt < 2; mt++) {
        int row = warpM*32 + mt*16 + g;
        #pragma unroll
        for (int nt = 0; nt < 4; nt++) {
            int col = h0 + warpN*32 + nt*8 + 2*tig;
            *(float2*)&dst[row*NS + col]     = make_float2(acc[mt][nt][0], acc[mt][nt][1]);
            *(float2*)&dst[(row+8)*NS + col] = make_float2(acc[mt][nt][2], acc[mt][nt][3]);
        }
    }
}

// ---------------- per-mode complex mix (mma): O = W @ X (complex), per (b,k) ----------------
// dyn smem: sWr 64*68 | sWi 64*68 | sXr 64*132 | sXi 64*132  => 102400 B
#define MIX_SMEM 102400
__global__ void __launch_bounds__(256) mixKm() {
    extern __shared__ __align__(16) char smem[];
    float* sWr = (float*)smem;
    float* sWi = (float*)(smem + 17408);
    float* sXr = (float*)(smem + 34816);
    float* sXi = (float*)(smem + 68608);
    int br = blockIdx.z;
    const float* Xin = br ? g_Xw : g_Xh;
    const float* Wr  = br ? g_wwA[0] : g_whA[0];
    const float* Wi  = br ? g_wwA[1] : g_whA[1];
    float* Out       = br ? g_Ow : g_Oh;
    int b = blockIdx.x >> 5, k = blockIdx.x & 31;
    int c0 = blockIdx.y * 128;
    int tid = threadIdx.x, lane = tid & 31, w = tid >> 5;
    int g = lane >> 2, tig = lane & 3;
    int warpM = w & 1, warpN = w >> 1;
    for (int idx = tid; idx < 4096; idx += 256) {
        int o = idx >> 6, i = idx & 63;
        sWr[o*68 + i] = Wr[k*4096 + o*64 + i];
        sWi[o*68 + i] = Wi[k*4096 + o*64 + i];
    }
    for (int idx = tid; idx < 8192; idx += 256) {
        int i = idx >> 7, c = idx & 127;
        const float* xb = Xin + ((size_t)(b*64 + i)*64 + 2*k)*NS + c0;
        sXr[i*132 + c] = stf(xb[c]);
        sXi[i*132 + c] = stf(xb[NS + c]);
    }
    __syncthreads();
    float accR[2][4][4] = {}, accI[2][4][4] = {};
    #pragma unroll
    for (int ks = 0; ks < 8; ks++) {
        int k0 = ks * 8;
        u32 ar[2][4], ai[2][4], nai[2][4];
        #pragma unroll
        for (int mt = 0; mt < 2; mt++) {
            int r0 = warpM*32 + mt*16;
            ar[mt][0] = __float_as_uint(sWr[(r0+g)*68 + k0 + tig]);
            ar[mt][1] = __float_as_uint(sWr[(r0+g+8)*68 + k0 + tig]);
            ar[mt][2] = __float_as_uint(sWr[(r0+g)*68 + k0 + tig + 4]);
            ar[mt][3] = __float_as_uint(sWr[(r0+g+8)*68 + k0 + tig + 4]);
            ai[mt][0] = __float_as_uint(sWi[(r0+g)*68 + k0 + tig]);
            ai[mt][1] = __float_as_uint(sWi[(r0+g+8)*68 + k0 + tig]);
            ai[mt][2] = __float_as_uint(sWi[(r0+g)*68 + k0 + tig + 4]);
            ai[mt][3] = __float_as_uint(sWi[(r0+g+8)*68 + k0 + tig + 4]);
            #pragma unroll
            for (int j = 0; j < 4; j++) nai[mt][j] = ai[mt][j] ^ 0x80000000u;
        }
        #pragma unroll
        for (int nt = 0; nt < 4; nt++) {
            int n0 = warpN*32 + nt*8;
            u32 bfr[2], bfi[2];
            bfr[0] = __float_as_uint(sXr[(k0+tig)*132 + n0 + g]);
            bfr[1] = __float_as_uint(sXr[(k0+tig+4)*132 + n0 + g]);
            bfi[0] = __float_as_uint(sXi[(k0+tig)*132 + n0 + g]);
            bfi[1] = __float_as_uint(sXi[(k0+tig+4)*132 + n0 + g]);
            #pragma unroll
            for (int mt = 0; mt < 2; mt++) {
                mma816(accR[mt][nt], ar[mt], bfr);
                mma816(accR[mt][nt], nai[mt], bfi);
                mma816(accI[mt][nt], ar[mt], bfi);
                mma816(accI[mt][nt], ai[mt], bfr);
            }
        }
    }
    #pragma unroll
    for (int mt = 0; mt < 2; mt++) {
        #pragma unroll
        for (int nt = 0; nt < 4; nt++) {
            int col = c0 + warpN*32 + nt*8 + 2*tig;
            int o0 = warpM*32 + mt*16 + g;
            float* ob0 = Out + ((size_t)(b*64 + o0)*64 + 2*k)*NS + col;
            *(float2*)ob0        = make_float2(accR[mt][nt][0], accR[mt][nt][1]);
            *(float2*)(ob0 + NS) = make_float2(accI[mt][nt][0], accI[mt][nt][1]);
            float* ob1 = Out + ((size_t)(b*64 + o0 + 8)*64 + 2*k)*NS + col;
            *(float2*)ob1        = make_float2(accR[mt][nt][2], accR[mt][nt][3]);
            *(float2*)(ob1 + NS) = make_float2(accI[mt][nt][2], accI[mt][nt][3]);
        }
    }
}

// ---------------- fused inverse DFTs (mma): f = IBh@Oh + OwT@IBw ----------------
// dyn smem: sAh 128*68 (34816) | sAw 128*69 (35328) | sBh 64*68 (17408) | sBw 64*68 (17408) => 104960 B
#define INV_SMEM 104960
__global__ void __launch_bounds__(256) invHWm() {
    extern __shared__ __align__(16) char smem[];
    float* sAh = (float*)smem;
    float* sAw = (float*)(smem + 34816);
    float* sBh = (float*)(smem + 70144);
    float* sBw = (float*)(smem + 87552);
    int slab = blockIdx.x;
    int h0 = (blockIdx.y >> 2) * 128, w0 = (blockIdx.y & 3) * 64;
    const float* Oh = g_Oh + (size_t)slab * 64 * NS;
    const float* Ow = g_Ow + (size_t)slab * 64 * NS;
    int tid = threadIdx.x, lane = tid & 31, w = tid >> 5;
    int g = lane >> 2, tig = lane & 3;
    int warpM = w >> 1, warpN = w & 1;     // 4 x 2
    for (int idx = tid; idx < 8192; idx += 256) {
        int r = idx >> 6, c = idx & 63;
        sAh[r*68 + c] = g_ibasis[(h0 + r)*64 + c];
    }
    for (int idx = tid; idx < 8192; idx += 256) {
        int ko = idx >> 7, hh = idx & 127;
        sAw[hh*69 + ko] = stf(Ow[ko*NS + h0 + hh]);
    }
    for (int idx = tid; idx < 4096; idx += 256) {
        int ko = idx >> 6, ww = idx & 63;
        sBh[ko*68 + ww] = stf(Oh[ko*NS + w0 + ww]);
        sBw[ko*68 + ww] = g_ibasisT[ko*NS + w0 + ww];
    }
    __syncthreads();
    float acc[2][4][4] = {};
    #pragma unroll
    for (int ks = 0; ks < 8; ks++) {
        int k0 = ks * 8;
        u32 ah[2][4], aw[2][4];
        #pragma unroll
        for (int mt = 0; mt < 2; mt++) {
            int r0 = warpM*32 + mt*16;
            ah[mt][0] = __float_as_uint(sAh[(r0+g)*68 + k0 + tig]);
            ah[mt][1] = __float_as_uint(sAh[(r0+g+8)*68 + k0 + tig]);
            ah[mt][2] = __float_as_uint(sAh[(r0+g)*68 + k0 + tig + 4]);
            ah[mt][3] = __float_as_uint(sAh[(r0+g+8)*68 + k0 + tig + 4]);
            aw[mt][0] = __float_as_uint(sAw[(r0+g)*69 + k0 + tig]);
            aw[mt][1] = __float_as_uint(sAw[(r0+g+8)*69 + k0 + tig]);
            aw[mt][2] = __float_as_uint(sAw[(r0+g)*69 + k0 + tig + 4]);
            aw[mt][3] = __float_as_uint(sAw[(r0+g+8)*69 + k0 + tig + 4]);
        }
        #pragma unroll
        for (int nt = 0; nt < 4; nt++) {
            int n0 = warpN*32 + nt*8;
            u32 bh[2], bw[2];
            bh[0] = __float_as_uint(sBh[(k0+tig)*68 + n0 + g]);
            bh[1] = __float_as_uint(sBh[(k0+tig+4)*68 + n0 + g]);
            bw[0] = __float_as_uint(sBw[(k0+tig)*68 + n0 + g]);
            bw[1] = __float_as_uint(sBw[(k0+tig+4)*68 + n0 + g]);
            #pragma unroll
            for (int mt = 0; mt < 2; mt++) {
                mma816(acc[mt][nt], ah[mt], bh);
                mma816(acc[mt][nt], aw[mt], bw);
            }
        }
    }
    __syncthreads();   // sAh dead; reuse as output staging [128][68]
    #pragma unroll
    for (int mt = 0; mt < 2; mt++) {
        int r0 = warpM*32 + mt*16 + g;
        #pragma unroll
        for (int nt = 0; nt < 4; nt++) {
            int col = warpN*32 + nt*8 + 2*tig;
            *(float2*)&sAh[r0*68 + col]     = make_float2(acc[mt][nt][0], acc[mt][nt][1]);
            *(float2*)&sAh[(r0+8)*68 + col] = make_float2(acc[mt][nt][2], acc[mt][nt][3]);
        }
    }
    __syncthreads();
    float* fp = g_f + (size_t)slab * HW;
    for (int idx = tid; idx < 8192; idx += 256) {
        int r = idx >> 6, c = idx & 63;
        fp[(size_t)(h0 + r)*NS + w0 + c] = sAh[r*68 + c];
    }
}

// ---------------- mma.sync tf32 FFN (unchanged, proven) ----------------
#define FFN_SMEM 90112
#define OFF_SA 2048
#define OFF_T1 19456
#define OFF_WB 53248

__global__ void __launch_bounds__(256) ffnM(const float* __restrict__ x,
        const float* __restrict__ w1, const float* __restrict__ b1,
        const float* __restrict__ lng, const float* __restrict__ lnb,
        const float* __restrict__ w2, const float* __restrict__ b2,
        float* __restrict__ out) {
    extern __shared__ __align__(16) char smem[];
    float* sVec = (float*)smem;
    float* sA = (float*)(smem + OFF_SA);
    float* sT = (float*)(smem + OFF_T1);
    float* sW = (float*)(smem + OFF_WB);
    int tid = threadIdx.x, lane = tid & 31, w = tid >> 5;
    int b  = blockIdx.x >> 10;
    int p0 = (blockIdx.x & 1023) * 64;

    if (tid < 128) { sVec[tid] = b1[tid]; sVec[128+tid] = lng[tid]; sVec[256+tid] = lnb[tid]; }
    if (tid < 64) sVec[384+tid] = b2[tid];
    for (int i = tid; i < 8192; i += 256) {
        int c = i >> 7, j = i & 127;
        sW[c*136 + j] = stf(w1[i]);
    }
    for (int i = tid; i < 4096; i += 256) {
        int c = i >> 6, px = i & 63;
        sA[px*68 + c] = stf(g_f[((size_t)(b*64 + c) << 16) + p0 + px]);
    }
    __syncthreads();

    int warpM = w & 1, warpN = w >> 1;
    int g = lane >> 2, tig = lane & 3;

    float acc[2][4][4] = {};
    #pragma unroll
    for (int ks = 0; ks < 8; ks++) {
        int k0 = ks * 8;
        u32 afr[2][4];
        #pragma unroll
        for (int mt = 0; mt < 2; mt++) {
            const float* ap = sA + (warpM*32 + mt*16)*68 + k0;
            afr[mt][0] = __float_as_uint(ap[g*68 + tig]);
            afr[mt][1] = __float_as_uint(ap[(g+8)*68 + tig]);
            afr[mt][2] = __float_as_uint(ap[g*68 + tig + 4]);
            afr[mt][3] = __float_as_uint(ap[(g+8)*68 + tig + 4]);
        }
        #pragma unroll
        for (int nt = 0; nt < 4; nt++) {
            const float* bp = sW + k0*136 + warpN*32 + nt*8;
            u32 bfr[2];
            bfr[0] = __float_as_uint(bp[tig*136 + g]);
            bfr[1] = __float_as_uint(bp[(tig+4)*136 + g]);
            mma816(acc[0][nt], afr[0], bfr);
            mma816(acc[1][nt], afr[1], bfr);
        }
    }
    #pragma unroll
    for (int mt = 0; mt < 2; mt++) {
        int r0 = warpM*32 + mt*16 + g;
        #pragma unroll
        for (int nt = 0; nt < 4; nt++) {
            int cb = warpN*32 + nt*8 + 2*tig;
            float bb0 = sVec[cb], bb1 = sVec[cb+1];
            sT[r0*132 + cb]     = fmaxf(acc[mt][nt][0] + bb0, 0.f);
            sT[r0*132 + cb + 1] = fmaxf(acc[mt][nt][1] + bb1, 0.f);
            sT[(r0+8)*132 + cb]     = fmaxf(acc[mt][nt][2] + bb0, 0.f);
            sT[(r0+8)*132 + cb + 1] = fmaxf(acc[mt][nt][3] + bb1, 0.f);
        }
    }
    __syncthreads();

    for (int p8 = 0; p8 < 8; p8++) {
        int px = w*8 + p8;
        float4 v = *(float4*)&sT[px*132 + lane*4];
        float s1 = v.x + v.y + v.z + v.w;
        float s2 = v.x*v.x + v.y*v.y + v.z*v.z + v.w*v.w;
        #pragma unroll
        for (int o = 16; o > 0; o >>= 1) {
            s1 += __shfl_xor_sync(0xFFFFFFFFu, s1, o);
            s2 += __shfl_xor_sync(0xFFFFFFFFu, s2, o);
        }
        float mu  = s1 * (1.0f/128.0f);
        float var = s2 * (1.0f/128.0f) - mu*mu;
        float inv = rsqrtf(var + 1e-5f);
        float4 gm = *(float4*)&sVec[128 + lane*4];
        float4 bt = *(float4*)&sVec[256 + lane*4];
        uint4 q;
        q.x = tf32b((v.x - mu)*inv*gm.x + bt.x);
        q.y = tf32b((v.y - mu)*inv*gm.y + bt.y);
        q.z = tf32b((v.z - mu)*inv*gm.z + bt.z);
        q.w = tf32b((v.w - mu)*inv*gm.w + bt.w);
        *(uint4*)&sT[px*132 + lane*4] = q;
    }
    __syncthreads();

    for (int i = tid; i < 8192; i += 256) {
        int j = i >> 6, o = i & 63;
        sW[j*72 + o] = stf(w2[i]);
    }
    __syncthreads();

    float acc2[2][2][4] = {};
    #pragma unroll
    for (int ks = 0; ks < 16; ks++) {
        int k0 = ks * 8;
        u32 afr[2][4];
        #pragma unroll
        for (int mt = 0; mt < 2; mt++) {
            const float* ap = sT + (warpM*32 + mt*16)*132 + k0;
            afr[mt][0] = __float_as_uint(ap[g*132 + tig]);
            afr[mt][1] = __float_as_uint(ap[(g+8)*132 + tig]);
            afr[mt][2] = __float_as_uint(ap[g*132 + tig + 4]);
            afr[mt][3] = __float_as_uint(ap[(g+8)*132 + tig + 4]);
        }
        #pragma unroll
        for (int nt = 0; nt < 2; nt++) {
            const float* bp = sW + k0*72 + warpN*16 + nt*8;
            u32 bfr[2];
            bfr[0] = __float_as_uint(bp[tig*72 + g]);
            bfr[1] = __float_as_uint(bp[(tig+4)*72 + g]);
            mma816(acc2[0][nt], afr[0], bfr);
            mma816(acc2[1][nt], afr[1], bfr);
        }
    }
    float* sO = sA;
    #pragma unroll
    for (int mt = 0; mt < 2; mt++) {
        int r0 = warpM*32 + mt*16 + g;
        #pragma unroll
        for (int nt = 0; nt < 2; nt++) {
            int ob = warpN*16 + nt*8 + 2*tig;
            float bb0 = sVec[384 + ob], bb1 = sVec[384 + ob + 1];
            sO[ob*68 + r0]       = acc2[mt][nt][0] + bb0;
            sO[(ob+1)*68 + r0]   = acc2[mt][nt][1] + bb1;
            sO[ob*68 + r0 + 8]   = acc2[mt][nt][2] + bb0;
            sO[(ob+1)*68 + r0+8] = acc2[mt][nt][3] + bb1;
        }
    }
    __syncthreads();
    for (int i = tid; i < 4096; i += 256) {
        int o = i >> 6, px = i & 63;
        size_t gg = ((size_t)(b*64 + o) << 16) + p0 + px;
        out[gg] = sO[o*68 + px] + x[gg];
    }
}

// ---------------- launch ----------------
extern "C" void kernel_launch(void* const* d_in, const int* in_sizes, int n_in,
                              void* d_out, int out_size) {
    const float* x    = (const float*)d_in[0];
    const float* whr  = (const float*)d_in[1];
    const float* whi  = (const float*)d_in[2];
    const float* wwr  = (const float*)d_in[3];
    const float* wwi  = (const float*)d_in[4];
    const float* fc1w = (const float*)d_in[5];
    const float* fc1b = (const float*)d_in[6];
    const float* lng  = (const float*)d_in[7];
    const float* lnb  = (const float*)d_in[8];
    const float* fc2w = (const float*)d_in[9];
    const float* fc2b = (const float*)d_in[10];
    float* out = (float*)d_out;

    cudaFuncSetAttribute(fdftHm, cudaFuncAttributeMaxDynamicSharedMemorySize, FDH_SMEM);
    cudaFuncSetAttribute(fdftWm, cudaFuncAttributeMaxDynamicSharedMemorySize, FDW_SMEM);
    cudaFuncSetAttribute(mixKm,  cudaFuncAttributeMaxDynamicSharedMemorySize, MIX_SMEM);
    cudaFuncSetAttribute(invHWm, cudaFuncAttributeMaxDynamicSharedMemorySize, INV_SMEM);
    cudaFuncSetAttribute(ffnM,   cudaFuncAttributeMaxDynamicSharedMemorySize, FFN_SMEM);

    initK<<<512, 256>>>(whr, whi, wwr, wwi);
    fdftHm<<<dim3(512, 2), 256, FDH_SMEM>>>(x);
    fdftWm<<<dim3(512, 2), 256, FDW_SMEM>>>(x);
    mixKm<<<dim3(256, 2, 2), 256, MIX_SMEM>>>();
    invHWm<<<dim3(512, 8), 256, INV_SMEM>>>();
    ffnM<<<8192, 256, FFN_SMEM>>>(x, fc1w, fc1b, lng, lnb, fc2w, fc2b, out);
}